// round 12
// baseline (speedup 1.0000x reference)
#include <cuda_runtime.h>

#define BB 2048
#define CC 9605
#define NT 256
#define NW (NT / 32)
#define NFULL 9            // nb >= 2400 = 9*256 + 96: iterations 0..8 always in bounds
#define NBATCH 3           // load-batch depth (6 LDG.128 in flight per thread)
#define CAP 1024
#define XTHRESH 2.4f
#define EPSF 1e-8f
#define LN2F 0.69314718055994531f
#define NEG_INF -3.402823e38f

__device__ float g_partials[BB];
__device__ int   g_done = 0;

// (base * w) in log2 units; y is exactly 0.0f or 1.0f so FFMA blends replace selects
__device__ __forceinline__ float term_bw2(float xv, float yv) {
    float p  = __fdividef(1.0f, 1.0f + __expf(-xv));   // sigmoid
    float xn = fminf(1.05f - p, 1.0f);                 // xs_neg
    float o  = fmaxf(p - 0.05f, 0.0f);                 // 1 - xs_neg
    float o2 = o * o;
    float o4 = o2 * o2;                                // (1-pt)^4 (neg)
    float arg = fmaf(yv, fmaxf(p, EPSF) - xn, xn);     // pos ? max(p,eps) : xn
    float w   = fmaf(yv, (1.0f - p) - o4, o4);         // pos ? (1-p) : o4
    return __log2f(arg) * w;                           // *ln2 folded at row level
}

__device__ __forceinline__ float term4(const float4& xv, const float4& yv) {
    return term_bw2(xv.x, yv.x) + term_bw2(xv.y, yv.y)
         + term_bw2(xv.z, yv.z) + term_bw2(xv.w, yv.w);
}

// monotone float->uint mapping so u64 key max == (max val, then min idx)
__device__ __forceinline__ unsigned long long pack_key(float v, int idx) {
    unsigned u = __float_as_uint(v);
    u = (u & 0x80000000u) ? ~u : (u | 0x80000000u);
    return ((unsigned long long)u << 32) | (unsigned)(0xFFFFFFFFu - (unsigned)idx);
}

__global__ __launch_bounds__(NT, 4)
void loss_kernel(const float* __restrict__ x, const float* __restrict__ y,
                 const int* __restrict__ ci, const int* __restrict__ ri,
                 const int* __restrict__ di, const int* __restrict__ wl,
                 float* __restrict__ out)
{
    const int row = blockIdx.x;
    const float* __restrict__ xr = x + (size_t)row * CC;
    const float* __restrict__ yr = y + (size_t)row * CC;

    // alignment prologue: row*CC % 4 == row % 4 -> peel p head elements
    const int p  = (4 - (row & 3)) & 3;
    const int nb = (CC - p) >> 2;                 // 2400 or 2401
    const int tail_start = p + 4 * nb;

    const float4* __restrict__ x4 = (const float4*)(xr + p);
    const float4* __restrict__ y4 = (const float4*)(yr + p);

    __shared__ float s_cval[CAP];
    __shared__ int   s_cidx[CAP];
    __shared__ int   s_count;
    __shared__ int   s_flags;
    __shared__ float s_wsum[NW];
    __shared__ int   s_sel[10];

    const int tid  = threadIdx.x;
    const int lane = tid & 31;
    const int wid  = tid >> 5;

    if (tid == 0) { s_count = 0; s_flags = 0; }
    __syncthreads();

    // per-sample ground-truth whitelist group flags (170 sparse y lookups)
    if (tid < 30) {
        if (yr[ci[tid]] > 0.5f) atomicOr(&s_flags, 1);
    } else if (tid < 100) {
        if (yr[ri[tid - 30]] > 0.5f) atomicOr(&s_flags, 2);
    } else if (tid < 170) {
        if (yr[di[tid - 100]] > 0.5f) atomicOr(&s_flags, 4);
    }

    // ── hot loop: batched loads (6 LDG.128 burst) then compute; 1-bit flags ──
    float acc = 0.0f;
    unsigned cmask = 0;
    #pragma unroll
    for (int mb = 0; mb < NFULL / NBATCH; mb++) {
        float4 xs[NBATCH], ys[NBATCH];
        #pragma unroll
        for (int j = 0; j < NBATCH; j++) {
            int i = tid + (mb * NBATCH + j) * NT;
            xs[j] = __ldcs(x4 + i);
            ys[j] = __ldcs(y4 + i);
        }
        #pragma unroll
        for (int j = 0; j < NBATCH; j++) {
            acc += term4(xs[j], ys[j]);
            float mx = fmaxf(fmaxf(xs[j].x, xs[j].y), fmaxf(xs[j].z, xs[j].w));
            cmask |= (mx > XTHRESH) ? (1u << (mb * NBATCH + j)) : 0u;
        }
    }
    {   // guarded final iteration (it = NFULL)
        int i = tid + NFULL * NT;
        if (i < nb) {
            float4 xv = __ldcs(x4 + i);
            float4 yv = __ldcs(y4 + i);
            acc += term4(xv, yv);
            float mx = fmaxf(fmaxf(xv.x, xv.y), fmaxf(xv.z, xv.w));
            cmask |= (mx > XTHRESH) ? (1u << NFULL) : 0u;
        }
    }

    // deferred candidate pushes: revisit only flagged iterations (avg < 0.1/thread)
    while (cmask) {
        int it = __ffs(cmask) - 1;
        cmask &= cmask - 1;
        int i = tid + it * NT;
        float4 xv = __ldg(x4 + i);                // L2-resident reload (usually)
        int nl = (xv.x > XTHRESH) + (xv.y > XTHRESH)
               + (xv.z > XTHRESH) + (xv.w > XTHRESH);
        int k = atomicAdd(&s_count, nl);
        int c0 = p + 4 * i;
        if (xv.x > XTHRESH) { if (k < CAP) { s_cval[k] = xv.x; s_cidx[k] = c0;     } k++; }
        if (xv.y > XTHRESH) { if (k < CAP) { s_cval[k] = xv.y; s_cidx[k] = c0 + 1; } k++; }
        if (xv.z > XTHRESH) { if (k < CAP) { s_cval[k] = xv.z; s_cidx[k] = c0 + 2; } k++; }
        if (xv.w > XTHRESH) { if (k < CAP) { s_cval[k] = xv.w; s_cidx[k] = c0 + 3; } }
    }

    // head (p elems) + tail (<=3 elems): thread 0
    if (tid == 0) {
        for (int c = 0; c < p; c++) {
            float xv = xr[c], yv = yr[c];
            acc += term_bw2(xv, yv);
            if (xv > XTHRESH) {
                int k = atomicAdd(&s_count, 1);
                if (k < CAP) { s_cval[k] = xv; s_cidx[k] = c; }
            }
        }
        for (int c = tail_start; c < CC; c++) {
            float xv = xr[c], yv = yr[c];
            acc += term_bw2(xv, yv);
            if (xv > XTHRESH) {
                int k = atomicAdd(&s_count, 1);
                if (k < CAP) { s_cval[k] = xv; s_cidx[k] = c; }
            }
        }
    }

    // warp partial sums
    #pragma unroll
    for (int o = 16; o > 0; o >>= 1) acc += __shfl_xor_sync(0xFFFFFFFFu, acc, o);
    if (lane == 0) s_wsum[wid] = acc;

    __syncthreads();          // candidates + flags + wsums visible
    if (wid != 0) return;     // warps 1..7 done; warp 0 finishes the row

    const int  cnt = s_count;
    const bool fb  = (cnt < 10) || (cnt > CAP);   // guaranteed-correct slow path

    if (!fb) {
        // 10 argmax passes over ~cnt candidates, u64 keys, warp-only
        for (int r = 0; r < 10; r++) {
            unsigned long long best = 0ull;
            for (int k = lane; k < cnt; k += 32) {
                unsigned long long key = pack_key(s_cval[k], s_cidx[k]);
                if (key > best) best = key;
            }
            #pragma unroll
            for (int o = 16; o > 0; o >>= 1) {
                unsigned long long t = __shfl_xor_sync(0xFFFFFFFFu, best, o);
                if (t > best) best = t;
            }
            int idx = (int)(0xFFFFFFFFu - (unsigned)best);
            if (lane == 0) s_sel[r] = idx;
            for (int k = lane; k < cnt; k += 32)
                if (s_cidx[k] == idx) s_cval[k] = NEG_INF;
            __syncwarp();
        }
    } else {
        // fallback: 10 argmax passes over the full row (never on this data)
        for (int r = 0; r < 10; r++) {
            unsigned long long best = 0ull;
            for (int c = lane; c < CC; c += 32) {
                bool used = false;
                for (int q = 0; q < r; q++) used |= (s_sel[q] == c);
                if (!used) {
                    unsigned long long key = pack_key(xr[c], c);
                    if (key > best) best = key;
                }
            }
            #pragma unroll
            for (int o = 16; o > 0; o >>= 1) {
                unsigned long long t = __shfl_xor_sync(0xFFFFFFFFu, best, o);
                if (t > best) best = t;
            }
            if (lane == 0) s_sel[r] = (int)(0xFFFFFFFFu - (unsigned)best);
            __syncwarp();
        }
    }

    // block sum (8 warp partials) via warp 0
    float bsum = (lane < NW) ? s_wsum[lane] : 0.0f;
    #pragma unroll
    for (int o = 16; o > 0; o >>= 1) bsum += __shfl_xor_sync(0xFFFFFFFFu, bsum, o);

    if (lane == 0) {
        // sequential 10-rank whitelist scan + correction
        int fl = s_flags;
        bool h1f = fl & 1, h2f = fl & 2, h3f = fl & 4;
        bool only4 = !(h1f || h2f || h3f);
        bool found = false;
        float fm[10];
        #pragma unroll
        for (int r = 0; r < 10; r++) {
            int j = s_sel[r];
            int wv = wl[j];
            bool in_map = wv > 0;
            bool in_gt = (wv == 1 && h1f) || (wv == 2 && h2f) ||
                         (wv == 3 && h3f) || (wv == 4 && only4);
            float f = 1.0f;
            if (in_map && only4) f *= 0.5f;                  // ALPHA_OTHER
            if (in_map && !in_gt && !found) f *= 2.0f;       // ALPHA1
            fm[r] = f;
            found = found || (in_map && in_gt);
        }
        float extra = found ? 1.0f : 2.0f;                   // post-scan ALPHA1
        float corr = 0.0f;
        #pragma unroll
        for (int r = 0; r < 10; r++) {
            float m = fm[r] * extra;
            if (m != 1.0f) {
                int j = s_sel[r];
                corr += term_bw2(xr[j], yr[j]) * (m - 1.0f);
            }
        }
        g_partials[row] = (bsum + corr) * LN2F;              // log2 -> ln
    }

    // last block fuses the final reduction (fixed-order -> deterministic)
    int done = 0;
    if (lane == 0) {
        __threadfence();
        done = atomicAdd(&g_done, 1);
    }
    done = __shfl_sync(0xFFFFFFFFu, done, 0);
    if (done == BB - 1) {
        __threadfence();
        float a = 0.0f;
        for (int k = lane; k < BB; k += 32) a += g_partials[k];
        #pragma unroll
        for (int o = 16; o > 0; o >>= 1) a += __shfl_xor_sync(0xFFFFFFFFu, a, o);
        if (lane == 0) {
            out[0] = -a;
            g_done = 0;        // reset for next graph replay
        }
    }
}

extern "C" void kernel_launch(void* const* d_in, const int* in_sizes, int n_in,
                              void* d_out, int out_size)
{
    const float* x  = (const float*)d_in[0];
    const float* y  = (const float*)d_in[1];
    const int*   ci = (const int*)d_in[2];
    const int*   ri = (const int*)d_in[3];
    const int*   di = (const int*)d_in[4];
    const int*   wl = (const int*)d_in[5];

    loss_kernel<<<BB, NT>>>(x, y, ci, ri, di, wl, (float*)d_out);
}